// round 7
// baseline (speedup 1.0000x reference)
#include <cuda_runtime.h>
#include <cstdint>

// ---------------- problem constants ----------------
#define Bb 8
#define Nn 131072          // F*T
#define Dd 40
#define P  48              // augmented row width (40 E + 4 V + 4 zero)
#define CELLS (P*P)        // 2304
#define CPB 54             // chunks per batch -> 432 CTAs ~ one wave @ 3/SM
#define CPBP 56            // padded chunk stride (floats), 16B aligned
#define CHUNK 2432         // 4 groups * 608 rows
#define GROWS 608          // rows per warp-group (pair)
#define TROWS 32           // rows per tile
#define GT 19              // tiles per group (608/32)
#define ROWB 224           // staged row stride (56 floats) -> conflict-free frags
#define SSTAGE (TROWS*ROWB)          // 7168 B per stage
#define SMEM_BYTES (4*2*SSTAGE)      // 4 groups x 2 stages = 57344 B -> 3 CTAs/SM
#define K2_BLOCKS 72

// ---------------- device scratch ----------------
// layout: g_partials[(cell*Bb + b)*CPBP + chunk]
__device__ __align__(16) float g_partials[(size_t)CELLS * Bb * CPBP];
__device__ float g_blocksums[K2_BLOCKS];

// ---------------- PTX helpers ----------------
__device__ __forceinline__ uint32_t smem_u32(const void* p) {
    uint32_t a;
    asm("{ .reg .u64 t; cvta.to.shared.u64 t, %1; cvt.u32.u64 %0, t; }"
        : "=r"(a) : "l"(p));
    return a;
}

#define CVT_TF32(u, f) asm("cvt.rna.tf32.f32 %0, %1;" : "=r"(u) : "f"(f))
#define LDSF(v, a)     asm volatile("ld.shared.f32 %0, [%1];" : "=f"(v) : "r"(a))
#define CPASYNC(dst, src, sz) \
    asm volatile("cp.async.cg.shared.global [%0], [%1], 16, %2;" \
                 :: "r"(dst), "l"(src), "r"(sz) : "memory")
#define CPCOMMIT() asm volatile("cp.async.commit_group;" ::: "memory")
#define CPWAIT1()  asm volatile("cp.async.wait_group 1;" ::: "memory")
#define CPWAIT0()  asm volatile("cp.async.wait_group 0;" ::: "memory")
#define BARSYNC64(id) asm volatile("bar.sync %0, 64;" :: "r"(id) : "memory")

// D(16x8) += A(16x8,row) * B(8x8,col), tf32 inputs, f32 accum
#define MMA_TF32(dp, a0, a1, a2, a3, b0, b1) \
    asm volatile("mma.sync.aligned.m16n8k8.row.col.f32.tf32.tf32.f32 " \
        "{%0,%1,%2,%3}, {%4,%5,%6,%7}, {%8,%9}, {%0,%1,%2,%3};" \
        : "+f"((dp)[0]), "+f"((dp)[1]), "+f"((dp)[2]), "+f"((dp)[3]) \
        : "r"(a0), "r"(a1), "r"(a2), "r"(a3), "r"(b0), "r"(b1))

// ---- each warp stages HALF of one 32-row tile ----
// E: 320 16B slots (contiguous in gmem); warp p takes 32-slot blocks 2i+p.
// V: 32 slots, staged by warp p=1. Rows >= nrem zero-fill via src-size 0.
__device__ __forceinline__ void stage_half(uint32_t sbase,
                                           const char* __restrict__ Ebase,
                                           const char* __restrict__ Vbase,
                                           int nrem, int lane, int p)
{
#pragma unroll
    for (int i = 0; i < 5; i++) {
        const int q = i * 64 + p * 32 + lane;
        const int r = q / 10;
        const uint32_t dst = (uint32_t)(q * 16 + r * 64);
        uint32_t sz = 16u;
        const char* src = Ebase + q * 16;
        if (r >= nrem) { sz = 0u; src = Ebase; }
        CPASYNC(sbase + dst, src, sz);
    }
    if (p) {
        const uint32_t dst = (uint32_t)(lane * ROWB + 160);
        uint32_t sz = 16u;
        const char* src = Vbase + lane * 16;
        if (lane >= nrem) { sz = 0u; src = Vbase; }
        CPASYNC(sbase + dst, src, sz);
    }
    CPCOMMIT();
}

// ============================================================
// Kernel 1: partial Gram G = X^T X per (batch, chunk), tf32 HMMA.
// Warp pairs share a double-buffered staging slab; each warp stages
// half the bytes and computes half the lower-triangle D tiles.
// ============================================================
__global__ __launch_bounds__(256, 3)
void gram_hmma_kernel(const float* __restrict__ E, const float* __restrict__ V)
{
    extern __shared__ float sm[];
    const int tid  = threadIdx.x;
    const int w    = tid >> 5;
    const int lane = tid & 31;
    const int g    = lane >> 2;   // group id 0..7
    const int tig  = lane & 3;    // thread in group
    const int gi   = w >> 1;      // warp-pair group 0..3
    const int p    = w & 1;       // parity within pair
    const int b     = blockIdx.y;
    const int chunk = blockIdx.x;

    // zero all smem once: feats 44..47 (+pad bytes) read as 0 forever
    {
        float4 z = make_float4(0.f, 0.f, 0.f, 0.f);
        for (int i = tid; i < SMEM_BYTES / 16; i += 256)
            ((float4*)sm)[i] = z;
    }
    __syncthreads();

    const int n_end  = min(Nn, (chunk + 1) * CHUNK);
    const int grp_n0 = chunk * CHUNK + gi * GROWS;
    const char* Eb = (const char*)(E + (size_t)b * Nn * Dd) + (size_t)grp_n0 * 160;
    const char* Vb = (const char*)(V + (size_t)b * Nn * 4) + (size_t)grp_n0 * 16;

    const uint32_t sgb = smem_u32(sm) + (uint32_t)(gi * 2 * SSTAGE);
    const int bar = gi + 1;

    // prologue: both warps stage their halves of tiles 0 and 1
    stage_half(sgb,          Eb,              Vb,             n_end - grp_n0,         lane, p);
    stage_half(sgb + SSTAGE, Eb + TROWS*160,  Vb + TROWS*16,  n_end - grp_n0 - TROWS, lane, p);

    float d[24];
#pragma unroll
    for (int k = 0; k < 24; k++) d[k] = 0.f;

    for (int t = 0; t < GT; t++) {
        if (t + 1 < GT) CPWAIT1();
        else            CPWAIT0();
        BARSYNC64(bar);            // partner's half also landed + fenced

        const uint32_t cb = sgb + (uint32_t)((t & 1) * SSTAGE);

#pragma unroll
        for (int kk = 0; kk < 4; kk++) {
            const uint32_t ra = cb + (uint32_t)((kk * 8 + tig) * ROWB + g * 4);
            if (p == 0) {
                float f0[4], f1[4];
                uint32_t u0[4], u1[4];
#pragma unroll
                for (int m = 0; m < 4; m++) {
                    LDSF(f0[m], ra + m * 32);
                    LDSF(f1[m], ra + 4 * ROWB + m * 32);
                }
#pragma unroll
                for (int m = 0; m < 4; m++) { CVT_TF32(u0[m], f0[m]); CVT_TF32(u1[m], f1[m]); }
                // tiles (mt,nt): (0,0)(0,1)(1,0)(1,1)(1,2)(1,3)
                MMA_TF32(&d[0],  u0[0], u0[1], u1[0], u1[1], u0[0], u1[0]);
                MMA_TF32(&d[4],  u0[0], u0[1], u1[0], u1[1], u0[1], u1[1]);
                MMA_TF32(&d[8],  u0[2], u0[3], u1[2], u1[3], u0[0], u1[0]);
                MMA_TF32(&d[12], u0[2], u0[3], u1[2], u1[3], u0[1], u1[1]);
                MMA_TF32(&d[16], u0[2], u0[3], u1[2], u1[3], u0[2], u1[2]);
                MMA_TF32(&d[20], u0[2], u0[3], u1[2], u1[3], u0[3], u1[3]);
            } else {
                float f0[6], f1[6];
                uint32_t u0[6], u1[6];
#pragma unroll
                for (int m = 0; m < 6; m++) {
                    LDSF(f0[m], ra + m * 32);
                    LDSF(f1[m], ra + 4 * ROWB + m * 32);
                }
#pragma unroll
                for (int m = 0; m < 6; m++) { CVT_TF32(u0[m], f0[m]); CVT_TF32(u1[m], f1[m]); }
                // tiles (2, 0..5)
                MMA_TF32(&d[0],  u0[4], u0[5], u1[4], u1[5], u0[0], u1[0]);
                MMA_TF32(&d[4],  u0[4], u0[5], u1[4], u1[5], u0[1], u1[1]);
                MMA_TF32(&d[8],  u0[4], u0[5], u1[4], u1[5], u0[2], u1[2]);
                MMA_TF32(&d[12], u0[4], u0[5], u1[4], u1[5], u0[3], u1[3]);
                MMA_TF32(&d[16], u0[4], u0[5], u1[4], u1[5], u0[4], u1[4]);
                MMA_TF32(&d[20], u0[4], u0[5], u1[4], u1[5], u0[5], u1[5]);
            }
        }
        BARSYNC64(bar);            // both warps done reading before overwrite

        if (t + 2 < GT)
            stage_half(cb, Eb + (size_t)(t + 2) * TROWS * 160,
                           Vb + (size_t)(t + 2) * TROWS * 16,
                           n_end - grp_n0 - (t + 2) * TROWS, lane, p);
    }

    CPWAIT0();

    // ---- fold 4 groups: all warps dump accs, warps 0/1 sum their parity ----
    __syncthreads();
    {
        float* fold = sm;          // 8*32*24 floats = 24KB, fits
        float* dst = fold + (size_t)(w * 32 + lane) * 24;
#pragma unroll
        for (int k = 0; k < 24; k++) dst[k] = d[k];
    }
    __syncthreads();

    if (w < 2) {
        const float* fold = sm;
#pragma unroll
        for (int k = 0; k < 24; k++) {
            float s = 0.f;
#pragma unroll
            for (int e = 0; e < 4; e++)
                s += fold[(size_t)(((w + 2 * e) * 32) + lane) * 24 + k];
            d[k] = s;
        }
        // write partials: warp 0 -> tiles mt{0,1}, warp 1 -> mt=2
        const int MT0[6] = {0,0,1,1,1,1};
        const int NT0[6] = {0,1,0,1,2,3};
#pragma unroll
        for (int f = 0; f < 6; f++) {
            const int i0 = (w == 0) ? (16 * MT0[f] + g) : (32 + g);
            const int j0 = ((w == 0) ? (8 * NT0[f]) : (8 * f)) + 2 * tig;
#pragma unroll
            for (int h = 0; h < 2; h++) {    // rows i0, i0+8
                const int cell0 = (i0 + 8 * h) * P + j0;
                g_partials[(size_t)(cell0 * Bb + b) * CPBP + chunk]       = d[f*4 + 2*h];
                g_partials[(size_t)((cell0 + 1) * Bb + b) * CPBP + chunk] = d[f*4 + 2*h + 1];
            }
        }
    }
}

// ============================================================
// Kernel 2: per-(cell,batch) chunk reduction + weighted square.
// Contiguous 54-float rows (13x float4 + 2). Mirrors skipped tiles.
// ============================================================
__global__ __launch_bounds__(256)
void reduce1_kernel()
{
    const int idx = blockIdx.x * 256 + threadIdx.x;   // idx = cell*Bb + b
    float v = 0.f;
    if (idx < Bb * CELLS) {
        const int cell = idx >> 3;
        const int b    = idx & 7;
        const int i = cell / P;
        const int j = cell - i * P;
        const bool kept = (j >> 3) <= 2 * (i >> 4) + 1;   // tile was computed
        const int rcell = kept ? cell : (j * P + i);
        const float* pf = &g_partials[(size_t)(rcell * Bb + b) * CPBP];
        const float4* p4 = (const float4*)pf;
        float s = 0.f;
#pragma unroll
        for (int q = 0; q < 13; q++) {
            float4 a = p4[q];
            s += (a.x + a.y) + (a.z + a.w);
        }
        s += pf[52] + pf[53];
        const float wgt = ((i < Dd) == (j < Dd)) ? 1.0f : -1.0f;
        v = wgt * s * s;
    }
    __shared__ float red[256];
    red[threadIdx.x] = v;
    __syncthreads();
#pragma unroll
    for (int h = 128; h > 0; h >>= 1) {
        if (threadIdx.x < h) red[threadIdx.x] += red[threadIdx.x + h];
        __syncthreads();
    }
    if (threadIdx.x == 0) g_blocksums[blockIdx.x] = red[0];
}

// ============================================================
// Kernel 3: final scalar.
// ============================================================
__global__ __launch_bounds__(128)
void reduce2_kernel(float* __restrict__ out)
{
    __shared__ float s[128];
    const int t = threadIdx.x;
    s[t] = (t < K2_BLOCKS) ? g_blocksums[t] : 0.f;
    __syncthreads();
#pragma unroll
    for (int h = 64; h > 0; h >>= 1) {
        if (t < h) s[t] += s[t + h];
        __syncthreads();
    }
    if (t == 0) out[0] = s[0] / (float)((size_t)Bb * Nn);
}

// ============================================================
extern "C" void kernel_launch(void* const* d_in, const int* in_sizes, int n_in,
                              void* d_out, int out_size)
{
    const float* E = (const float*)d_in[0];
    const float* V = (const float*)d_in[1];
    if (n_in >= 2 && in_sizes[0] < in_sizes[1]) {
        const float* tmp = E; E = V; V = tmp;
    }

    cudaFuncSetAttribute(gram_hmma_kernel,
                         cudaFuncAttributeMaxDynamicSharedMemorySize, SMEM_BYTES);

    dim3 grid1(CPB, Bb);
    gram_hmma_kernel<<<grid1, 256, SMEM_BYTES>>>(E, V);
    reduce1_kernel<<<K2_BLOCKS, 256>>>();
    reduce2_kernel<<<1, 128>>>((float*)d_out);
}